// round 6
// baseline (speedup 1.0000x reference)
#include <cuda_runtime.h>

// Problem shapes (fixed by the dataset problem)
#define BB 8
#define CC 64
#define HH 256
#define WW 256
#define HW (HH*WW)       // 65536

// Tile geometry: 32 wide x 8 tall, one pixel per thread (256 threads).
#define TTX 32
#define TTY 8
#define GXX (TTX+6)      // 38: gray region width  (halo 3)
#define GYY (TTY+6)      // 14: gray region height
#define DXX (TTX+2)      // 34: DoG region width   (halo 1)
#define DYY (TTY+2)      // 10: DoG region height

// ---------------------------------------------------------------------------
// Fully fused kernel:
//   gray = mean_c(x)  ->  DoG(5x5, zero-pad)  ->  Sobel(3x3, zero-pad on DoG)
//   -> mag -> sigmoid gate -> out = x * (1 + att)
// Each thread owns one output pixel and holds its 64 channel values of x in
// REGISTERS from the gray phase to the multiply phase, so x is read from DRAM
// exactly once. Halo grays are recomputed from x; those lines are first-touched
// by neighboring (concurrently resident) blocks, so they come from L2.
// ---------------------------------------------------------------------------
__global__ void __launch_bounds__(256, 2)
fused_kernel(const float* __restrict__ x,
             const float* __restrict__ gw,
             const float* __restrict__ gbv,
             float* __restrict__ out) {
    __shared__ float sg[GYY][GXX + 2];   // gray tile + halo 3 (padded cols)
    __shared__ float sd[DYY][DXX + 2];   // dog tile + halo 1
    __shared__ float kd[25];             // DoG weights (gk1 - gk2)

    const int tx  = threadIdx.x;         // 0..31
    const int ty  = threadIdx.y;         // 0..7
    const int tid = ty * 32 + tx;

    if (tid == 0) {
        // Build normalized gaussian kernels exactly like the reference (fp32).
        float w1[25], w2[25];
        float s1 = 0.f, s2 = 0.f;
        #pragma unroll
        for (int i = 0; i < 25; ++i) {
            float dx = (float)(i / 5) - 2.0f;
            float dy = (float)(i % 5) - 2.0f;
            float r2 = dx * dx + dy * dy;
            float a = expf(-r2 * 0.5f);     // sigma = 1
            float b = expf(-r2 * 0.125f);   // sigma = 2
            w1[i] = a; w2[i] = b;
            s1 += a;  s2 += b;
        }
        float i1 = 1.0f / s1, i2 = 1.0f / s2;
        #pragma unroll
        for (int i = 0; i < 25; ++i) kd[i] = w1[i] * i1 - w2[i] * i2;
    }

    const int b  = blockIdx.z;
    const int x0 = blockIdx.x * TTX;
    const int y0 = blockIdx.y * TTY;

    // ---- Phase 1a: own pixel — load all 64 channels into registers, sum ----
    const size_t basep = (size_t)b * CC * HW + (size_t)(y0 + ty) * WW + (x0 + tx);
    float v[CC];
    #pragma unroll
    for (int c = 0; c < CC; ++c) v[c] = __ldg(x + basep + (size_t)c * HW);

    float s = 0.f;
    #pragma unroll
    for (int c = 0; c < CC; ++c) s += v[c];
    sg[ty + 3][tx + 3] = s * (1.0f / (float)CC);

    // ---- Phase 1b: halo gray ring (recompute from x; mostly L2 hits) ----
    for (int i = tid; i < GYY * GXX; i += 256) {
        int r = i / GXX, c = i % GXX;
        if (r >= 3 && r < 3 + TTY && c >= 3 && c < 3 + TTX) continue;  // interior done
        int gy = y0 - 3 + r, gx = x0 - 3 + c;
        float acc = 0.f;
        if ((unsigned)gy < HH && (unsigned)gx < WW) {
            const float* p = x + (size_t)b * CC * HW + (size_t)gy * WW + gx;
            #pragma unroll 8
            for (int cc = 0; cc < CC; ++cc) acc += __ldg(p + (size_t)cc * HW);
        }
        sg[r][c] = acc * (1.0f / (float)CC);
    }
    __syncthreads();

    // ---- Phase 2: DoG on tile + halo(1); out-of-image DoG forced to 0 ----
    for (int i = tid; i < DYY * DXX; i += 256) {
        int r = i / DXX, c = i % DXX;
        int gy = y0 - 1 + r, gx = x0 - 1 + c;
        float vv = 0.f;
        if ((unsigned)gy < HH && (unsigned)gx < WW) {
            float acc = 0.f;
            #pragma unroll
            for (int ki = 0; ki < 5; ++ki)
                #pragma unroll
                for (int kj = 0; kj < 5; ++kj)
                    acc += kd[ki * 5 + kj] * sg[r + ki][c + kj];
            vv = acc;
        }
        sd[r][c] = vv;
    }
    __syncthreads();

    // ---- Phase 3: Sobel -> magnitude -> sigmoid gate (own pixel) ----
    float d00 = sd[ty    ][tx    ], d01 = sd[ty    ][tx + 1], d02 = sd[ty    ][tx + 2];
    float d10 = sd[ty + 1][tx    ],                            d12 = sd[ty + 1][tx + 2];
    float d20 = sd[ty + 2][tx    ], d21 = sd[ty + 2][tx + 1], d22 = sd[ty + 2][tx + 2];
    float gxv = (d02 - d00) + 2.0f * (d12 - d10) + (d22 - d20);
    float gyv = (d20 - d00) + 2.0f * (d21 - d01) + (d22 - d02);
    float mag = sqrtf(gxv * gxv + gyv * gyv + 1e-6f);
    float tv  = mag * gw[0] + gbv[0];
    float att = 1.0f + 1.0f / (1.0f + expf(-tv));

    // ---- Phase 4: out = x * att, straight from registers ----
    float* po = out + basep;
    #pragma unroll
    for (int c = 0; c < CC; ++c) po[(size_t)c * HW] = v[c] * att;
}

// ---------------------------------------------------------------------------
extern "C" void kernel_launch(void* const* d_in, const int* in_sizes, int n_in,
                              void* d_out, int out_size) {
    const float* x  = (const float*)d_in[0];
    const float* gw = (const float*)d_in[1];
    const float* gb = (const float*)d_in[2];
    float* out = (float*)d_out;

    dim3 grid(WW / TTX, HH / TTY, BB);   // 8 x 32 x 8 = 2048 blocks
    dim3 block(TTX, TTY);                // 256 threads, 1 pixel each
    fused_kernel<<<grid, block>>>(x, gw, gb, out);
}

// round 7
// speedup vs baseline: 1.4696x; 1.4696x over previous
#include <cuda_runtime.h>

// Problem shapes (fixed by the dataset problem)
#define BB 8
#define CC 64
#define HH 256
#define WW 256
#define HW (HH*WW)       // 65536

// Tile geometry: 32 wide x 16 tall, 512 threads.
#define TTX 32
#define TTY 16
#define NT  512
#define GXX (TTX+6)      // 38: gray region width  (halo 3)
#define GYY (TTY+6)      // 22: gray region height
#define GN  (GXX*GYY)    // 836
#define DXX (TTX+2)      // 34: DoG region width   (halo 1)
#define DYY (TTY+2)      // 18: DoG region height
#define DN  (DXX*DYY)    // 612

// ---------------------------------------------------------------------------
// Fully fused, no register staging:
//   gray = mean_c(x) over tile+halo(3)   [x read #1: DRAM first-touch]
//   -> DoG(5x5, zero-pad) -> Sobel(3x3, zero-pad on DoG) -> att in smem
//   -> out = x * (1 + att)               [x read #2: L1/L2 hit, float4]
// Halo gray loads land in L2 (neighbor blocks stream the same lines
// concurrently), so DRAM traffic ~= one read of x + one write of out.
// ---------------------------------------------------------------------------
__global__ void __launch_bounds__(NT)
fused_kernel(const float* __restrict__ x,
             const float* __restrict__ gw,
             const float* __restrict__ gbv,
             float* __restrict__ out) {
    __shared__ float sg[GYY][GXX + 2];   // gray region (padded cols)
    __shared__ float sd[DYY][DXX + 2];   // dog region
    __shared__ float sa[TTY][TTX];       // att (1 + sigmoid), row-major
    __shared__ float kd[25];             // DoG weights (gk1 - gk2)

    const int tid = threadIdx.x;

    if (tid == 0) {
        // Build normalized gaussian kernels exactly like the reference (fp32).
        float w1[25], w2[25];
        float s1 = 0.f, s2 = 0.f;
        #pragma unroll
        for (int i = 0; i < 25; ++i) {
            float dx = (float)(i / 5) - 2.0f;
            float dy = (float)(i % 5) - 2.0f;
            float r2 = dx * dx + dy * dy;
            float a = expf(-r2 * 0.5f);     // sigma = 1
            float b = expf(-r2 * 0.125f);   // sigma = 2
            w1[i] = a; w2[i] = b;
            s1 += a;  s2 += b;
        }
        float i1 = 1.0f / s1, i2 = 1.0f / s2;
        #pragma unroll
        for (int i = 0; i < 25; ++i) kd[i] = w1[i] * i1 - w2[i] * i2;
    }

    const int b  = blockIdx.z;
    const int x0 = blockIdx.x * TTX;
    const int y0 = blockIdx.y * TTY;
    const float* xb = x + (size_t)b * CC * HW;

    // ---- Phase 1: gray over the full 38x22 region (interior + halo) ----
    // Warp covers 32 consecutive positions in 38-wide rows -> <=2 segments.
    for (int i = tid; i < GN; i += NT) {
        int r = i / GXX, c = i - r * GXX;
        int gy = y0 - 3 + r, gx = x0 - 3 + c;
        float acc = 0.f;
        if ((unsigned)gy < HH && (unsigned)gx < WW) {
            const float* p = xb + (size_t)gy * WW + gx;
            float a0 = 0.f, a1 = 0.f, a2 = 0.f, a3 = 0.f;
            #pragma unroll
            for (int cc = 0; cc < CC; cc += 4) {
                a0 += __ldg(p + (size_t)(cc + 0) * HW);
                a1 += __ldg(p + (size_t)(cc + 1) * HW);
                a2 += __ldg(p + (size_t)(cc + 2) * HW);
                a3 += __ldg(p + (size_t)(cc + 3) * HW);
            }
            acc = (a0 + a1) + (a2 + a3);
        }
        sg[r][c] = acc * (1.0f / (float)CC);
    }
    __syncthreads();

    // ---- Phase 2: DoG on tile + halo(1); out-of-image DoG forced to 0 ----
    for (int i = tid; i < DN; i += NT) {
        int r = i / DXX, c = i - r * DXX;
        int gy = y0 - 1 + r, gx = x0 - 1 + c;
        float vv = 0.f;
        if ((unsigned)gy < HH && (unsigned)gx < WW) {
            float acc = 0.f;
            #pragma unroll
            for (int ki = 0; ki < 5; ++ki)
                #pragma unroll
                for (int kj = 0; kj < 5; ++kj)
                    acc += kd[ki * 5 + kj] * sg[r + ki][c + kj];
            vv = acc;
        }
        sd[r][c] = vv;
    }
    __syncthreads();

    // ---- Phase 3: Sobel -> magnitude -> sigmoid gate (one pixel/thread) ----
    {
        const int py = tid >> 5;       // 0..15
        const int px = tid & 31;       // 0..31
        float d00 = sd[py    ][px    ], d01 = sd[py    ][px + 1], d02 = sd[py    ][px + 2];
        float d10 = sd[py + 1][px    ],                            d12 = sd[py + 1][px + 2];
        float d20 = sd[py + 2][px    ], d21 = sd[py + 2][px + 1], d22 = sd[py + 2][px + 2];
        float gxv = (d02 - d00) + 2.0f * (d12 - d10) + (d22 - d20);
        float gyv = (d20 - d00) + 2.0f * (d21 - d01) + (d22 - d02);
        float mag = sqrtf(gxv * gxv + gyv * gyv + 1e-6f);
        float tv  = mag * gw[0] + gbv[0];
        sa[py][px] = 1.0f + 1.0f / (1.0f + expf(-tv));
    }
    __syncthreads();

    // ---- Phase 4: out = x * att, float4, re-read of x hits L1/L2 ----
    // Tile per channel = 16 rows x 8 float4; 8192 float4 total, 16 per thread.
    #pragma unroll 4
    for (int f = tid; f < (TTY * TTX / 4) * CC; f += NT) {
        int c  = f >> 7;               // channel
        int q  = f & 127;              // float4 slot within tile
        int r  = q >> 3;               // row 0..15
        int c4 = (q & 7) << 2;         // col 0,4,...,28
        size_t off = (size_t)c * HW + (size_t)(y0 + r) * WW + (x0 + c4);
        float4 v = __ldg((const float4*)(xb + off));
        float4 a = *(const float4*)&sa[r][c4];
        v.x *= a.x; v.y *= a.y; v.z *= a.z; v.w *= a.w;
        *(float4*)(out + (size_t)b * CC * HW + off) = v;
    }
}

// ---------------------------------------------------------------------------
extern "C" void kernel_launch(void* const* d_in, const int* in_sizes, int n_in,
                              void* d_out, int out_size) {
    const float* x  = (const float*)d_in[0];
    const float* gw = (const float*)d_in[1];
    const float* gb = (const float*)d_in[2];
    float* out = (float*)d_out;

    dim3 grid(WW / TTX, HH / TTY, BB);   // 8 x 16 x 8 = 1024 blocks
    fused_kernel<<<grid, NT>>>(x, gw, gb, out);
}